// round 13
// baseline (speedup 1.0000x reference)
#include <cuda_runtime.h>
#include <cuda_bf16.h>

// HATS constants (fixed by the problem definition)
#define KCELL   10
#define RR      3
#define SSZ     7          // 2R+1
#define NBINS   98         // 2 * S * S
#define HISTP   100        // padded hist row
#define GWW     24         // W / K
#define NCELLS  432        // (H/K)*(W/K) = 18*24
#define TAU_INV (1.0f / 1e6f)
#define DT_MAX  1e5f

#define CSPLIT  18         // blocks per batch == grid rows; block owns one row
#define CPB     24         // cells per block == GWW (one full grid row)
#define CAP     32         // max events kept per cell (mean ~4.7, P(>=32)~1e-15)
#define NTHR    512        // 16 warps
#define WPB     16
#define UNROLL  4          // event loads in flight per thread

// Exact v/10 for 0 <= v < 256: one IMAD + one SHF.
__device__ __forceinline__ int div10(int v) { return (v * 205) >> 11; }

// ---------------------------------------------------------------------------
// Single kernel, no global scratch. Block (b, s) owns grid ROW s of batch b
// (cells s*24 .. s*24+23). Phase 1 scans the batch with unconditional batched
// loads; the row filter is two float compares on e.y. Phase 2: one warp per
// cell does the n^2 causal pair loop and writes the normalized histogram
// with float2 stores (output rows are 392 B -> 8-byte aligned, NOT 16).
// ---------------------------------------------------------------------------
__global__ __launch_bounds__(NTHR)
void hats_onekernel(const float4* __restrict__ ev,
                    const int* __restrict__ lengths,
                    float* __restrict__ out, int T) {
    __shared__ int   scnt[CPB];
    __shared__ uint2 sbuk[CPB][CAP];   // .x = t bits, .y = x|y<<8|p<<16|idx<<17
    __shared__ float hist[WPB][HISTP];

    int tid  = threadIdx.x;
    int warp = tid >> 5;
    int lane = tid & 31;
    int b  = blockIdx.x / CSPLIT;
    int s  = blockIdx.x - b * CSPLIT;
    float ylo = (float)(s * KCELL);            // row filter bounds (exact)
    float yhi = (float)(s * KCELL + KCELL);

    for (int k = tid; k < CPB; k += NTHR) scnt[k] = 0;

    int len = lengths[b];              // overlaps with the event loads below
    const float4* evb = ev + (size_t)b * T;
    __syncthreads();

    // ---- Phase 1: scan all T events, batched independent loads ----
    for (int i0 = 0; i0 < T; i0 += NTHR * UNROLL) {
        float4 e[UNROLL];
        int    idx[UNROLL];
        #pragma unroll
        for (int k = 0; k < UNROLL; k++) {
            idx[k] = i0 + k * NTHR + tid;
            if (idx[k] < T) e[k] = evb[idx[k]];
        }
        #pragma unroll
        for (int k = 0; k < UNROLL; k++) {
            int i = idx[k];
            // Row filter: two FSETP on the raw float (y integer-valued).
            if (e[k].y >= ylo && e[k].y < yhi && i < len) {
                int xi = (int)e[k].x, yi = (int)e[k].y;
                int cl = div10(xi);                    // column within row
                int slot = atomicAdd(&scnt[cl], 1);
                if (slot < CAP) {
                    uint2 v;
                    v.x = __float_as_uint(e[k].z);
                    v.y = (unsigned)xi | ((unsigned)yi << 8)
                        | ((unsigned)(int)e[k].w << 16) | ((unsigned)i << 17);
                    sbuk[cl][slot] = v;
                }
            }
        }
    }
    __syncthreads();

    // ---- Phase 2: per-cell pairwise surfaces, one warp per cell ----
    for (int cl = warp; cl < CPB; cl += WPB) {
        int rawcnt = scnt[cl];
        int n = rawcnt < CAP ? rawcnt : CAP;

        for (int k = lane; k < HISTP; k += 32) hist[warp][k] = 0.0f;
        __syncwarp();

        int np = n * n;
        float rn = n > 0 ? __frcp_rn((float)n) : 0.0f;
        for (int p = lane; p < np; p += 32) {
            int a = __float2int_rd((float)p * rn);       // ~ p / n
            if (a * n > p) a--;                          // fixup (rcp rounding)
            else if ((a + 1) * n <= p) a++;
            int c = p - a * n;                           // contributor j
            uint2 va = sbuk[cl][a];
            uint2 vc = sbuk[cl][c];
            if ((vc.y >> 17) > (va.y >> 17)) continue;   // causal: idx_j <= idx_i
            float dt = __uint_as_float(va.x) - __uint_as_float(vc.x);  // >= 0
            if (dt > DT_MAX) continue;
            int dx = (int)(vc.y & 0xFF)        - (int)(va.y & 0xFF)        + RR;
            int dy = (int)((vc.y >> 8) & 0xFF) - (int)((va.y >> 8) & 0xFF) + RR;
            int pa = (va.y >> 16) & 1, pc = (vc.y >> 16) & 1;
            if ((unsigned)dx < SSZ && (unsigned)dy < SSZ && pa == pc) {
                int bin = (pa * SSZ + dy) * SSZ + dx;
                atomicAdd(&hist[warp][bin], __expf(-dt * TAU_INV));
            }
        }
        __syncwarp();

        // float2 epilogue: 49 8-byte stores cover 98 floats; out rows are
        // 392 B so every cell base is 8-byte aligned (NOT 16 -> no float4).
        float inv = 1.0f / fmaxf((float)rawcnt, 1.0f);
        float* obase = out + (size_t)(b * NCELLS + s * CPB + cl) * NBINS;
        #pragma unroll
        for (int k = lane; k < NBINS / 2; k += 32) {     // k = 0..48
            float2 h2 = *(const float2*)&hist[warp][k * 2];
            h2.x *= inv; h2.y *= inv;
            *(float2*)(obase + k * 2) = h2;
        }
        __syncwarp();
    }
}

// ---------------------------------------------------------------------------
// Launch
// ---------------------------------------------------------------------------
extern "C" void kernel_launch(void* const* d_in, const int* in_sizes, int n_in,
                              void* d_out, int out_size) {
    const float4* ev = (const float4*)d_in[0];  // [B, T, 4] = (x, y, t, p)
    const int* lengths = (const int*)d_in[1];   // [B]
    float* out = (float*)d_out;                 // [B, NC, 2, S, S] float32

    int B = in_sizes[1];
    int T = in_sizes[0] / (4 * B);

    hats_onekernel<<<B * CSPLIT, NTHR>>>(ev, lengths, out, T);
}

// round 14
// speedup vs baseline: 1.0294x; 1.0294x over previous
#include <cuda_runtime.h>
#include <cuda_bf16.h>

// HATS constants (fixed by the problem definition)
#define KCELL   10
#define RR      3
#define SSZ     7          // 2R+1
#define NBINS   98         // 2 * S * S
#define HISTP   100        // padded hist row
#define GWW     24         // W / K
#define NCELLS  432        // (H/K)*(W/K) = 18*24
#define TAU_INV (1.0f / 1e6f)
#define DT_MAX  1e5f

#define CSPLIT  18         // blocks per batch == grid rows; block owns one row
#define CPB     24         // cells per block == GWW (one full grid row)
#define CAP     32         // max events kept per cell (mean ~4.7)
#define NTHR    1024       // 32 warps -> phase 2 is exactly 1 cell per warp
#define UNROLL  2          // NTHR*UNROLL == T: single scan iteration, 2 loads

// Exact v/10 for 0 <= v < 256: one IMAD + one SHF.
__device__ __forceinline__ int div10(int v) { return (v * 205) >> 11; }

// ---------------------------------------------------------------------------
// Single kernel, no global scratch. Block (b, s) owns grid ROW s of batch b
// (cells s*24 .. s*24+23). Phase 1 scans the batch with 2 unconditional
// batched loads per thread; row filter = two float compares on e.y.
// Phase 2: one warp per cell (32 warps, 24 cells) does the n^2 causal pair
// loop and writes the normalized histogram with float2 stores.
// ---------------------------------------------------------------------------
__global__ __launch_bounds__(NTHR)
void hats_onekernel(const float4* __restrict__ ev,
                    const int* __restrict__ lengths,
                    float* __restrict__ out, int T) {
    __shared__ int   scnt[CPB];
    __shared__ uint2 sbuk[CPB][CAP];   // .x = t bits, .y = x|y<<8|p<<16|idx<<17
    __shared__ float hist[CPB][HISTP];

    int tid  = threadIdx.x;
    int warp = tid >> 5;
    int lane = tid & 31;
    int b  = blockIdx.x / CSPLIT;
    int s  = blockIdx.x - b * CSPLIT;
    float ylo = (float)(s * KCELL);            // row filter bounds (exact)
    float yhi = (float)(s * KCELL + KCELL);

    if (tid < CPB) scnt[tid] = 0;

    int len = lengths[b];              // overlaps with the event loads below
    const float4* evb = ev + (size_t)b * T;
    __syncthreads();

    // ---- Phase 1: scan all T events, 2 independent loads per thread ----
    for (int i0 = 0; i0 < T; i0 += NTHR * UNROLL) {
        float4 e[UNROLL];
        int    idx[UNROLL];
        #pragma unroll
        for (int k = 0; k < UNROLL; k++) {
            idx[k] = i0 + k * NTHR + tid;
            if (idx[k] < T) e[k] = evb[idx[k]];
        }
        #pragma unroll
        for (int k = 0; k < UNROLL; k++) {
            int i = idx[k];
            // Row filter: two FSETP on the raw float (y integer-valued).
            if (e[k].y >= ylo && e[k].y < yhi && i < len) {
                int xi = (int)e[k].x, yi = (int)e[k].y;
                int cl = div10(xi);                    // column within row
                int slot = atomicAdd(&scnt[cl], 1);
                if (slot < CAP) {
                    uint2 v;
                    v.x = __float_as_uint(e[k].z);
                    v.y = (unsigned)xi | ((unsigned)yi << 8)
                        | ((unsigned)(int)e[k].w << 16) | ((unsigned)i << 17);
                    sbuk[cl][slot] = v;
                }
            }
        }
    }
    __syncthreads();

    // ---- Phase 2: one warp per cell (warps 24..31 idle) ----
    int cl = warp;
    if (cl < CPB) {
        int rawcnt = scnt[cl];
        int n = rawcnt < CAP ? rawcnt : CAP;

        for (int k = lane; k < HISTP; k += 32) hist[cl][k] = 0.0f;
        __syncwarp();

        int np = n * n;
        float rn = n > 0 ? __frcp_rn((float)n) : 0.0f;
        for (int p = lane; p < np; p += 32) {
            int a = __float2int_rd((float)p * rn);       // ~ p / n
            if (a * n > p) a--;                          // fixup (rcp rounding)
            else if ((a + 1) * n <= p) a++;
            int c = p - a * n;                           // contributor j
            uint2 va = sbuk[cl][a];
            uint2 vc = sbuk[cl][c];
            if ((vc.y >> 17) > (va.y >> 17)) continue;   // causal: idx_j <= idx_i
            float dt = __uint_as_float(va.x) - __uint_as_float(vc.x);  // >= 0
            if (dt > DT_MAX) continue;
            int dx = (int)(vc.y & 0xFF)        - (int)(va.y & 0xFF)        + RR;
            int dy = (int)((vc.y >> 8) & 0xFF) - (int)((va.y >> 8) & 0xFF) + RR;
            int pa = (va.y >> 16) & 1, pc = (vc.y >> 16) & 1;
            if ((unsigned)dx < SSZ && (unsigned)dy < SSZ && pa == pc) {
                int bin = (pa * SSZ + dy) * SSZ + dx;
                atomicAdd(&hist[cl][bin], __expf(-dt * TAU_INV));
            }
        }
        __syncwarp();

        // float2 epilogue: 49 8-byte stores; cell rows are 392 B (8B-aligned).
        float inv = 1.0f / fmaxf((float)rawcnt, 1.0f);
        float* obase = out + (size_t)(b * NCELLS + s * CPB + cl) * NBINS;
        #pragma unroll
        for (int k = lane; k < NBINS / 2; k += 32) {     // k = 0..48
            float2 h2 = *(const float2*)&hist[cl][k * 2];
            h2.x *= inv; h2.y *= inv;
            *(float2*)(obase + k * 2) = h2;
        }
    }
}

// ---------------------------------------------------------------------------
// Launch
// ---------------------------------------------------------------------------
extern "C" void kernel_launch(void* const* d_in, const int* in_sizes, int n_in,
                              void* d_out, int out_size) {
    const float4* ev = (const float4*)d_in[0];  // [B, T, 4] = (x, y, t, p)
    const int* lengths = (const int*)d_in[1];   // [B]
    float* out = (float*)d_out;                 // [B, NC, 2, S, S] float32

    int B = in_sizes[1];
    int T = in_sizes[0] / (4 * B);

    hats_onekernel<<<B * CSPLIT, NTHR>>>(ev, lengths, out, T);
}